// round 1
// baseline (speedup 1.0000x reference)
#include <cuda_runtime.h>
#include <math.h>

#define N_USERS 50000
#define N_ENT   150000
#define NNODES  200000
#define D       64
#define NEDGE   3200000
#define BATCH   4096

// -------- scratch (device globals; no allocation allowed) --------
__device__ float    g_s1[NNODES];
__device__ float    g_s2[NNODES];
__device__ float    g_denom[NNODES];
__device__ float    g_acc[(size_t)NNODES * D];     // 51.2 MB, only needed rows used
__device__ float    g_hout[(size_t)NNODES * D];    // 51.2 MB, only needed rows used
__device__ unsigned g_flag[(NNODES + 31) / 32];    // needed-dst bitset (25 KB)
__device__ int      g_uniq[2 * BATCH];             // unique needed nodes (<= 8192)
__device__ int      g_nuniq;
__device__ int      g_nce;                         // compacted edge count
__device__ unsigned g_maxenc;                      // encoded global max of e
__device__ int      g_ce_src[NEDGE];
__device__ int      g_ce_dst[NEDGE];
__device__ float    g_ce_e[NEDGE];
__device__ float    g_v1[D], g_v2[D];
__device__ float    g_c1, g_c2;

__device__ __forceinline__ const float2* feat2(int n, const float* ue, const float* ee) {
    return (n < N_USERS) ? (const float2*)ue + (size_t)n * 32
                         : (const float2*)ee + (size_t)(n - N_USERS) * 32;
}

// -------- K0: zero flags + counters --------
__global__ void k_zero() {
    int tid = blockIdx.x * blockDim.x + threadIdx.x;
    int stride = gridDim.x * blockDim.x;
    const int NW = (NNODES + 31) / 32;
    for (int i = tid; i < NW; i += stride) g_flag[i] = 0u;
    if (tid == 0) { g_nuniq = 0; g_nce = 0; g_maxenc = 0u; }
}

// -------- K1: v1 = W_att @ a[:D], v2 = W_att @ a[D:], c1 = b·a[:D], c2 = b·a[D:] --------
__global__ void k_prep(const float* __restrict__ Wa, const float* __restrict__ ba,
                       const float* __restrict__ a) {
    int k = threadIdx.x;
    if (k < D) {
        float v1 = 0.f, v2 = 0.f;
        for (int j = 0; j < D; j++) {
            float w = Wa[k * D + j];
            v1 += w * a[j];
            v2 += w * a[D + j];
        }
        g_v1[k] = v1; g_v2[k] = v2;
    }
    if (k == 0) {
        float c1 = 0.f, c2 = 0.f;
        for (int j = 0; j < D; j++) { c1 += ba[j] * a[j]; c2 += ba[j] * a[D + j]; }
        g_c1 = c1; g_c2 = c2;
    }
}

// -------- K2: mark needed nodes, build unique list, zero their acc/denom rows --------
__global__ void k_mark(const int* __restrict__ uid, const int* __restrict__ iid) {
    int i = blockIdx.x * blockDim.x + threadIdx.x;
    if (i >= 2 * BATCH) return;
    int node = (i < BATCH) ? uid[i] : N_USERS + iid[i - BATCH];
    unsigned bit = 1u << (node & 31);
    unsigned old = atomicOr(&g_flag[node >> 5], bit);
    if (!(old & bit)) {
        int slot = atomicAdd(&g_nuniq, 1);
        g_uniq[slot] = node;
        g_denom[node] = 0.f;
        float* row = g_acc + (size_t)node * D;
        #pragma unroll
        for (int d = 0; d < D; d++) row[d] = 0.f;
    }
}

// -------- K3: per-node attention scalars s1, s2 (warp per node) --------
__global__ void k_s(const float* __restrict__ ue, const float* __restrict__ ee) {
    int lane = threadIdx.x & 31;
    int wg = (blockIdx.x * blockDim.x + threadIdx.x) >> 5;
    int nwarps = (gridDim.x * blockDim.x) >> 5;
    float2 v1 = ((const float2*)g_v1)[lane];
    float2 v2 = ((const float2*)g_v2)[lane];
    float c1 = g_c1, c2 = g_c2;
    for (int n = wg; n < NNODES; n += nwarps) {
        float2 f = feat2(n, ue, ee)[lane];
        float p1 = f.x * v1.x + f.y * v1.y;
        float p2 = f.x * v2.x + f.y * v2.y;
        #pragma unroll
        for (int o = 16; o > 0; o >>= 1) {
            p1 += __shfl_xor_sync(0xFFFFFFFFu, p1, o);
            p2 += __shfl_xor_sync(0xFFFFFFFFu, p2, o);
        }
        if (lane == 0) { g_s1[n] = p1 + c1; g_s2[n] = p2 + c2; }
    }
}

// -------- K4: edge pass 1 — logits, global max, compaction of needed edges --------
__global__ void __launch_bounds__(256) k_edge1(const int* __restrict__ idx) {
    const int tid = threadIdx.x;
    const int gtid = blockIdx.x * blockDim.x + tid;
    const int nth = gridDim.x * blockDim.x;
    const int iters = (NEDGE + nth - 1) / nth;
    const int lane = tid & 31, wid = tid >> 5;
    __shared__ int sWarpBase[8];
    __shared__ int sBlockBase;
    __shared__ float sMax[8];
    float lmax = -1e30f;
    for (int it = 0; it < iters; ++it) {
        int e = it * nth + gtid;
        int src = 0, dst = 0; float ev = 0.f; bool take = false;
        if (e < NEDGE) {
            src = idx[e];
            dst = idx[NEDGE + e];
            float s = g_s1[src] + g_s2[dst];
            ev = (s > 0.f) ? s : 0.2f * s;
            lmax = fmaxf(lmax, ev);
            take = (g_flag[dst >> 5] >> (dst & 31)) & 1u;
        }
        unsigned m = __ballot_sync(0xFFFFFFFFu, take);
        if (lane == 0) sWarpBase[wid] = __popc(m);
        __syncthreads();
        if (tid == 0) {
            int t = 0;
            #pragma unroll
            for (int w = 0; w < 8; w++) { int c = sWarpBase[w]; sWarpBase[w] = t; t += c; }
            sBlockBase = t ? atomicAdd(&g_nce, t) : 0;
        }
        __syncthreads();
        if (take) {
            int pos = sBlockBase + sWarpBase[wid] + __popc(m & ((1u << lane) - 1u));
            g_ce_src[pos] = src; g_ce_dst[pos] = dst; g_ce_e[pos] = ev;
        }
        __syncthreads();
    }
    #pragma unroll
    for (int o = 16; o > 0; o >>= 1) lmax = fmaxf(lmax, __shfl_xor_sync(0xFFFFFFFFu, lmax, o));
    if (lane == 0) sMax[wid] = lmax;
    __syncthreads();
    if (wid == 0) {
        float m2 = (lane < 8) ? sMax[lane] : -1e30f;
        #pragma unroll
        for (int o = 4; o > 0; o >>= 1) m2 = fmaxf(m2, __shfl_xor_sync(0xFFFFFFFFu, m2, o));
        if (lane == 0) {
            unsigned u = __float_as_uint(m2);
            u = (u & 0x80000000u) ? ~u : (u | 0x80000000u);
            atomicMax(&g_maxenc, u);
        }
    }
}

// -------- K5: edge pass 2 (compacted edges) — exp, denom, weighted-feat scatter --------
__global__ void k_edge2(const float* __restrict__ ue, const float* __restrict__ ee) {
    int lane = threadIdx.x & 31;
    int wg = (blockIdx.x * blockDim.x + threadIdx.x) >> 5;
    int nwarps = (gridDim.x * blockDim.x) >> 5;
    unsigned u = g_maxenc;
    float gmax = __uint_as_float((u & 0x80000000u) ? (u & 0x7FFFFFFFu) : ~u);
    int nce = g_nce;
    for (int w = wg; w < nce; w += nwarps) {
        int src = g_ce_src[w];
        int dst = g_ce_dst[w];
        float ex = __expf(g_ce_e[w] - gmax);
        float2 f = feat2(src, ue, ee)[lane];
        float* dest = g_acc + (size_t)dst * D + 2 * lane;
        atomicAdd(dest,     f.x * ex);
        atomicAdd(dest + 1, f.y * ex);
        if (lane == 0) atomicAdd(&g_denom[dst], ex);
    }
}

// -------- K6: per-needed-node epilogue (W1/W2 matvecs, lrelu, normalize) --------
__global__ void __launch_bounds__(256) k_node(const float* __restrict__ ue, const float* __restrict__ ee,
                                              const float* __restrict__ W1, const float* __restrict__ b1,
                                              const float* __restrict__ W2, const float* __restrict__ b2) {
    __shared__ float sW1[D * D], sW2[D * D], sb1[D], sb2[D];
    __shared__ float sg[8][D];
    int tid = threadIdx.x, lane = tid & 31, wid = tid >> 5;
    for (int i = tid; i < D * D; i += blockDim.x) { sW1[i] = W1[i]; sW2[i] = W2[i]; }
    for (int i = tid; i < D; i += blockDim.x) { sb1[i] = b1[i]; sb2[i] = b2[i]; }
    __syncthreads();
    int nu = g_nuniq;
    int wg = (blockIdx.x * blockDim.x + tid) >> 5;
    int nwarps = (gridDim.x * blockDim.x) >> 5;
    for (int q = wg; q < nu; q += nwarps) {
        __syncwarp();
        int n = g_uniq[q];
        float den = g_denom[n];
        float inv = 1.f / (den + 1e-9f);
        float sden = den * inv;
        float2 a2 = ((const float2*)(g_acc + (size_t)n * D))[lane];
        sg[wid][2 * lane] = a2.x * inv;
        sg[wid][2 * lane + 1] = a2.y * inv;
        __syncwarp();
        float n0 = sden * sb1[2 * lane], n1 = sden * sb1[2 * lane + 1];
        #pragma unroll 16
        for (int k = 0; k < D; k++) {
            float gk = sg[wid][k];
            float2 wr = ((const float2*)(sW1 + k * D))[lane];
            n0 += gk * wr.x; n1 += gk * wr.y;
        }
        float2 hs = feat2(n, ue, ee)[lane];
        float sum0 = hs.x + n0, sum1 = hs.y + n1;
        float p0 = hs.x * n0, p1 = hs.y * n1;
        __syncwarp();
        sg[wid][2 * lane] = p0;
        sg[wid][2 * lane + 1] = p1;
        __syncwarp();
        float z0 = sum0 + sb2[2 * lane], z1 = sum1 + sb2[2 * lane + 1];
        #pragma unroll 16
        for (int k = 0; k < D; k++) {
            float pk = sg[wid][k];
            float2 wr = ((const float2*)(sW2 + k * D))[lane];
            z0 += pk * wr.x; z1 += pk * wr.y;
        }
        float h0 = (z0 > 0.f) ? z0 : 0.2f * z0;
        float h1 = (z1 > 0.f) ? z1 : 0.2f * z1;
        float ss = h0 * h0 + h1 * h1;
        #pragma unroll
        for (int o = 16; o > 0; o >>= 1) ss += __shfl_xor_sync(0xFFFFFFFFu, ss, o);
        float invn = 1.f / fmaxf(sqrtf(ss), 1e-12f);
        float* orow = g_hout + (size_t)n * D;
        orow[2 * lane] = h0 * invn;
        orow[2 * lane + 1] = h1 * invn;
    }
}

// -------- K7: final pair dots (warp per pair) --------
__global__ void k_final(const int* __restrict__ uid, const int* __restrict__ iid,
                        const float* __restrict__ ue, const float* __restrict__ ee,
                        float* __restrict__ out) {
    int lane = threadIdx.x & 31;
    int wg = (blockIdx.x * blockDim.x + threadIdx.x) >> 5;
    int nwarps = (gridDim.x * blockDim.x) >> 5;
    for (int p = wg; p < BATCH; p += nwarps) {
        int un = uid[p];
        int in = N_USERS + iid[p];
        float2 fu = feat2(un, ue, ee)[lane];
        float2 fi = feat2(in, ue, ee)[lane];
        float acc = fu.x * fi.x + fu.y * fi.y;
        float2 hu = ((const float2*)(g_hout + (size_t)un * D))[lane];
        float2 hi = ((const float2*)(g_hout + (size_t)in * D))[lane];
        acc += hu.x * hi.x + hu.y * hi.y;
        #pragma unroll
        for (int o = 16; o > 0; o >>= 1) acc += __shfl_xor_sync(0xFFFFFFFFu, acc, o);
        if (lane == 0) out[p] = acc;
    }
}

extern "C" void kernel_launch(void* const* d_in, const int* in_sizes, int n_in,
                              void* d_out, int out_size) {
    const int* idx = (const int*)d_in[0];
    const int* uid = (const int*)d_in[1];
    const int* iid = (const int*)d_in[2];
    // num_nodes may be passed as a scalar input at slot 3 (size 1) or omitted.
    int base = (in_sizes[3] <= 2) ? 4 : 3;
    const float* ue = (const float*)d_in[base + 0];
    const float* ee = (const float*)d_in[base + 1];
    const float* Wa = (const float*)d_in[base + 2];
    const float* ba = (const float*)d_in[base + 3];
    const float* W1 = (const float*)d_in[base + 4];
    const float* b1 = (const float*)d_in[base + 5];
    const float* W2 = (const float*)d_in[base + 6];
    const float* b2 = (const float*)d_in[base + 7];
    const float* a  = (const float*)d_in[base + 8];
    float* out = (float*)d_out;
    (void)n_in; (void)out_size;

    k_zero<<<32, 256>>>();
    k_prep<<<1, 64>>>(Wa, ba, a);
    k_mark<<<32, 256>>>(uid, iid);
    k_s<<<2048, 256>>>(ue, ee);
    k_edge1<<<2048, 256>>>(idx);
    k_edge2<<<1184, 256>>>(ue, ee);
    k_node<<<64, 256>>>(ue, ee, W1, b1, W2, b2);
    k_final<<<128, 256>>>(uid, iid, ue, ee, out);
}

// round 4
// speedup vs baseline: 1.4730x; 1.4730x over previous
#include <cuda_runtime.h>
#include <math.h>

#define N_USERS 50000
#define N_ENT   150000
#define NNODES  200000
#define D       64
#define NEDGE   3200000
#define BATCH   4096

// -------- scratch (device globals; no allocation allowed) --------
__device__ float    g_s1[NNODES];
__device__ float    g_s2[NNODES];
__device__ float    g_denom[NNODES];
__device__ float    g_acc[(size_t)NNODES * D];
__device__ float    g_hout[(size_t)NNODES * D];
__device__ unsigned g_flag[(NNODES + 31) / 32];
__device__ int      g_uniq[2 * BATCH];
__device__ int      g_nuniq;
__device__ int      g_nce;
__device__ int      g_ce_src[NEDGE / 8];   // expected ~131k << 400k
__device__ int      g_ce_dst[NEDGE / 8];
__device__ float    g_v1[D], g_v2[D];
__device__ float    g_c1, g_c2;

__device__ __forceinline__ const float2* feat2(int n, const float* ue, const float* ee) {
    return (n < N_USERS) ? (const float2*)ue + (size_t)n * 32
                         : (const float2*)ee + (size_t)(n - N_USERS) * 32;
}
__device__ __forceinline__ const float4* feat4(int n, const float* ue, const float* ee) {
    return (n < N_USERS) ? (const float4*)ue + (size_t)n * 16
                         : (const float4*)ee + (size_t)(n - N_USERS) * 16;
}

// -------- K0: zero flags/counters + compute v1,v2,c1,c2 --------
__global__ void k_init(const float* __restrict__ Wa, const float* __restrict__ ba,
                       const float* __restrict__ a) {
    int tid = blockIdx.x * blockDim.x + threadIdx.x;
    int stride = gridDim.x * blockDim.x;
    const int NW = (NNODES + 31) / 32;
    for (int i = tid; i < NW; i += stride) g_flag[i] = 0u;
    if (tid == 0) { g_nuniq = 0; g_nce = 0; }
    if (blockIdx.x == 0) {
        int k = threadIdx.x;
        if (k < D) {
            float v1 = 0.f, v2 = 0.f;
            for (int j = 0; j < D; j++) {
                float w = Wa[k * D + j];
                v1 += w * a[j];
                v2 += w * a[D + j];
            }
            g_v1[k] = v1; g_v2[k] = v2;
        }
        if (k == 0) {
            float c1 = 0.f, c2 = 0.f;
            for (int j = 0; j < D; j++) { c1 += ba[j] * a[j]; c2 += ba[j] * a[D + j]; }
            g_c1 = c1; g_c2 = c2;
        }
    }
}

// -------- K1: mark needed nodes, build unique list, zero their acc/denom --------
__global__ void k_mark(const int* __restrict__ uid, const int* __restrict__ iid) {
    int i = blockIdx.x * blockDim.x + threadIdx.x;
    if (i >= 2 * BATCH) return;
    int node = (i < BATCH) ? uid[i] : N_USERS + iid[i - BATCH];
    unsigned bit = 1u << (node & 31);
    unsigned old = atomicOr(&g_flag[node >> 5], bit);
    if (!(old & bit)) {
        int slot = atomicAdd(&g_nuniq, 1);
        g_uniq[slot] = node;
        g_denom[node] = 0.f;
        float* row = g_acc + (size_t)node * D;
        #pragma unroll
        for (int d = 0; d < D; d++) row[d] = 0.f;
    }
}

// -------- K2: per-node attention scalars (float4 loads, 4 rows / warp / iter) --------
__global__ void __launch_bounds__(256) k_s(const float* __restrict__ ue, const float* __restrict__ ee) {
    int lane = threadIdx.x & 31;
    int half = lane >> 4;
    int l = lane & 15;
    int wg = (blockIdx.x * blockDim.x + threadIdx.x) >> 5;
    int nwarps = (gridDim.x * blockDim.x) >> 5;
    float4 v1 = ((const float4*)g_v1)[l];
    float4 v2 = ((const float4*)g_v2)[l];
    float c1 = g_c1, c2 = g_c2;
    for (int n = wg * 4; n < NNODES; n += nwarps * 4) {   // NNODES % 4 == 0
        int ra = n + half;
        int rb = n + 2 + half;
        float4 fa = feat4(ra, ue, ee)[l];
        float4 fb = feat4(rb, ue, ee)[l];
        float a1 = fa.x * v1.x + fa.y * v1.y + fa.z * v1.z + fa.w * v1.w;
        float a2 = fa.x * v2.x + fa.y * v2.y + fa.z * v2.z + fa.w * v2.w;
        float b1 = fb.x * v1.x + fb.y * v1.y + fb.z * v1.z + fb.w * v1.w;
        float b2 = fb.x * v2.x + fb.y * v2.y + fb.z * v2.z + fb.w * v2.w;
        #pragma unroll
        for (int o = 8; o; o >>= 1) {
            a1 += __shfl_xor_sync(0xFFFFFFFFu, a1, o);
            a2 += __shfl_xor_sync(0xFFFFFFFFu, a2, o);
            b1 += __shfl_xor_sync(0xFFFFFFFFu, b1, o);
            b2 += __shfl_xor_sync(0xFFFFFFFFu, b2, o);
        }
        if (l == 0) {
            g_s1[ra] = a1 + c1; g_s2[ra] = a2 + c2;
            g_s1[rb] = b1 + c1; g_s2[rb] = b2 + c2;
        }
    }
}

// -------- K3: edge pass 1 — flag-test stream + block-aggregated compaction --------
// (same control structure as the R1-passing k_edge1, minus s-gathers and max)
__global__ void __launch_bounds__(256) k_edge1(const int* __restrict__ idx) {
    const int tid = threadIdx.x;
    const int gtid = blockIdx.x * blockDim.x + tid;
    const int nth = gridDim.x * blockDim.x;
    const int iters = (NEDGE + nth - 1) / nth;
    const int lane = tid & 31, wid = tid >> 5;
    __shared__ int sWarpBase[8];
    __shared__ int sBlockBase;
    for (int it = 0; it < iters; ++it) {
        int e = it * nth + gtid;
        int src = 0, dst = 0; bool take = false;
        if (e < NEDGE) {
            src = idx[e];
            dst = idx[NEDGE + e];
            take = (g_flag[dst >> 5] >> (dst & 31)) & 1u;
        }
        unsigned m = __ballot_sync(0xFFFFFFFFu, take);
        if (lane == 0) sWarpBase[wid] = __popc(m);
        __syncthreads();
        if (tid == 0) {
            int t = 0;
            #pragma unroll
            for (int w = 0; w < 8; w++) { int c = sWarpBase[w]; sWarpBase[w] = t; t += c; }
            sBlockBase = t ? atomicAdd(&g_nce, t) : 0;
        }
        __syncthreads();
        if (take) {
            int pos = sBlockBase + sWarpBase[wid] + __popc(m & ((1u << lane) - 1u));
            if (pos < NEDGE / 8) { g_ce_src[pos] = src; g_ce_dst[pos] = dst; }
        }
        __syncthreads();
    }
}

// -------- K4: edge pass 2 (compacted) — logits, exp, denom + feat scatter --------
__global__ void k_edge2(const float* __restrict__ ue, const float* __restrict__ ee) {
    int lane = threadIdx.x & 31;
    int wg = (blockIdx.x * blockDim.x + threadIdx.x) >> 5;
    int nwarps = (gridDim.x * blockDim.x) >> 5;
    int nce = g_nce;
    if (nce > NEDGE / 8) nce = NEDGE / 8;
    for (int w = wg; w < nce; w += nwarps) {
        int src = g_ce_src[w];
        int dst = g_ce_dst[w];
        float ev = g_s1[src] + g_s2[dst];
        ev = (ev > 0.f) ? ev : 0.2f * ev;
        float ex = __expf(ev);
        float2 f = feat2(src, ue, ee)[lane];
        float* dest = g_acc + (size_t)dst * D + 2 * lane;
        atomicAdd(dest,     f.x * ex);
        atomicAdd(dest + 1, f.y * ex);
        if (lane == 0) atomicAdd(&g_denom[dst], ex);
    }
}

// -------- K5: per-needed-node epilogue (unchanged from R1-passing version) --------
__global__ void __launch_bounds__(256) k_node(const float* __restrict__ ue, const float* __restrict__ ee,
                                              const float* __restrict__ W1, const float* __restrict__ b1,
                                              const float* __restrict__ W2, const float* __restrict__ b2) {
    __shared__ float sW1[D * D], sW2[D * D], sb1[D], sb2[D];
    __shared__ float sg[8][D];
    int tid = threadIdx.x, lane = tid & 31, wid = tid >> 5;
    for (int i = tid; i < D * D; i += blockDim.x) { sW1[i] = W1[i]; sW2[i] = W2[i]; }
    for (int i = tid; i < D; i += blockDim.x) { sb1[i] = b1[i]; sb2[i] = b2[i]; }
    __syncthreads();
    int nu = g_nuniq;
    int wg = (blockIdx.x * blockDim.x + tid) >> 5;
    int nwarps = (gridDim.x * blockDim.x) >> 5;
    for (int q = wg; q < nu; q += nwarps) {
        __syncwarp();
        int n = g_uniq[q];
        float den = g_denom[n];
        float inv = 1.f / (den + 1e-9f);
        float sden = den * inv;
        float2 a2 = ((const float2*)(g_acc + (size_t)n * D))[lane];
        sg[wid][2 * lane] = a2.x * inv;
        sg[wid][2 * lane + 1] = a2.y * inv;
        __syncwarp();
        float n0 = sden * sb1[2 * lane], n1 = sden * sb1[2 * lane + 1];
        #pragma unroll 16
        for (int k = 0; k < D; k++) {
            float gk = sg[wid][k];
            float2 wr = ((const float2*)(sW1 + k * D))[lane];
            n0 += gk * wr.x; n1 += gk * wr.y;
        }
        float2 hs = feat2(n, ue, ee)[lane];
        float sum0 = hs.x + n0, sum1 = hs.y + n1;
        float p0 = hs.x * n0, p1 = hs.y * n1;
        __syncwarp();
        sg[wid][2 * lane] = p0;
        sg[wid][2 * lane + 1] = p1;
        __syncwarp();
        float z0 = sum0 + sb2[2 * lane], z1 = sum1 + sb2[2 * lane + 1];
        #pragma unroll 16
        for (int k = 0; k < D; k++) {
            float pk = sg[wid][k];
            float2 wr = ((const float2*)(sW2 + k * D))[lane];
            z0 += pk * wr.x; z1 += pk * wr.y;
        }
        float h0 = (z0 > 0.f) ? z0 : 0.2f * z0;
        float h1 = (z1 > 0.f) ? z1 : 0.2f * z1;
        float ss = h0 * h0 + h1 * h1;
        #pragma unroll
        for (int o = 16; o > 0; o >>= 1) ss += __shfl_xor_sync(0xFFFFFFFFu, ss, o);
        float invn = 1.f / fmaxf(sqrtf(ss), 1e-12f);
        float* orow = g_hout + (size_t)n * D;
        orow[2 * lane] = h0 * invn;
        orow[2 * lane + 1] = h1 * invn;
    }
}

// -------- K6: final pair dots (unchanged from R1-passing version) --------
__global__ void k_final(const int* __restrict__ uid, const int* __restrict__ iid,
                        const float* __restrict__ ue, const float* __restrict__ ee,
                        float* __restrict__ out) {
    int lane = threadIdx.x & 31;
    int wg = (blockIdx.x * blockDim.x + threadIdx.x) >> 5;
    int nwarps = (gridDim.x * blockDim.x) >> 5;
    for (int p = wg; p < BATCH; p += nwarps) {
        int un = uid[p];
        int in = N_USERS + iid[p];
        float2 fu = feat2(un, ue, ee)[lane];
        float2 fi = feat2(in, ue, ee)[lane];
        float acc = fu.x * fi.x + fu.y * fi.y;
        float2 hu = ((const float2*)(g_hout + (size_t)un * D))[lane];
        float2 hi = ((const float2*)(g_hout + (size_t)in * D))[lane];
        acc += hu.x * hi.x + hu.y * hi.y;
        #pragma unroll
        for (int o = 16; o > 0; o >>= 1) acc += __shfl_xor_sync(0xFFFFFFFFu, acc, o);
        if (lane == 0) out[p] = acc;
    }
}

extern "C" void kernel_launch(void* const* d_in, const int* in_sizes, int n_in,
                              void* d_out, int out_size) {
    const int* idx = (const int*)d_in[0];
    const int* uid = (const int*)d_in[1];
    const int* iid = (const int*)d_in[2];
    int base = (in_sizes[3] <= 2) ? 4 : 3;   // skip num_nodes scalar if present
    const float* ue = (const float*)d_in[base + 0];
    const float* ee = (const float*)d_in[base + 1];
    const float* Wa = (const float*)d_in[base + 2];
    const float* ba = (const float*)d_in[base + 3];
    const float* W1 = (const float*)d_in[base + 4];
    const float* b1 = (const float*)d_in[base + 5];
    const float* W2 = (const float*)d_in[base + 6];
    const float* b2 = (const float*)d_in[base + 7];
    const float* a  = (const float*)d_in[base + 8];
    float* out = (float*)d_out;
    (void)n_in; (void)out_size;

    k_init<<<64, 256>>>(Wa, ba, a);
    k_mark<<<32, 256>>>(uid, iid);
    k_s<<<2048, 256>>>(ue, ee);
    k_edge1<<<2048, 256>>>(idx);
    k_edge2<<<1184, 256>>>(ue, ee);
    k_node<<<128, 256>>>(ue, ee, W1, b1, W2, b2);
    k_final<<<128, 256>>>(uid, iid, ue, ee, out);
}